// round 11
// baseline (speedup 1.0000x reference)
#include <cuda_runtime.h>
#include <cstdint>

#define HH 512
#define WW 512
#define MAXB 16
#define MAXBN 512
#define NCH 4                  // H-chunks per slab
#define CHROWS (HH / NCH)      // 128 rows per chunk

#define STAGES 4               // pipeline depth
#define SROWS 8                // rows per stage
#define STAGE_BYTES (SROWS * WW * 4)       // 16384
#define NSTG (CHROWS / SROWS)              // 16 stages per chunk

// dynamic smem layout (bytes)
#define SU_OFF    0            // 128 floats
#define SU2_OFF   512          // 128 floats
#define SCOL_OFF  1024         // 512 floats
#define GRP_OFF   3072         // 4 unsigned
#define SRED_OFF  3088         // 16 floats
#define SVERT_OFF 3152         // 4 floats
#define MBAR_OFF  3200         // 4 x uint64 (8-aligned)
#define BUF_OFF   4096         // STAGES x 16384
#define SMEM_DYN  (BUF_OFF + STAGES * STAGE_BYTES)   // 69632

// Scratch (device globals — zero-initialized; no allocation).
__device__ int    g_xmin [MAXB * HH];
__device__ int    g_xmax [MAXB * HH];
__device__ float4 g_theta[MAXB];                 // {sl_l, ic_l, sl_r, ic_r}
__device__ int    g_count[MAXB];                 // minmax->fit election
__device__ float  g_colp [MAXBN][NCH][WW];       // per-chunk column sums
__device__ float  g_part [MAXBN][NCH][2];        // per-chunk {inst, vert}
__device__ int    g_cnt  [MAXBN];                // size-chunk combine election

// ---- minimal PTX helpers ----
__device__ __forceinline__ uint32_t smem_u32(const void* p) {
    uint32_t a;
    asm("{ .reg .u64 t; cvta.to.shared.u64 t, %1; cvt.u32.u64 %0, t; }"
        : "=r"(a) : "l"(p));
    return a;
}
#define MBAR_INIT(addr, cnt) \
    asm volatile("mbarrier.init.shared.b64 [%0], %1;" :: "r"(addr), "r"(cnt) : "memory")
#define MBAR_EXPECT_TX(addr, bytes) \
    asm volatile("mbarrier.arrive.expect_tx.shared.b64 _, [%0], %1;" \
                 :: "r"(addr), "r"(bytes) : "memory")
#define BULK_G2S(dst, src, bytes, mbar) \
    asm volatile("cp.async.bulk.shared::cluster.global.mbarrier::complete_tx::bytes " \
                 "[%0], [%1], %2, [%3];" \
                 :: "r"(dst), "l"(src), "r"(bytes), "r"(mbar) : "memory")
__device__ __forceinline__ void mbar_wait_parity(uint32_t addr, uint32_t parity) {
    uint32_t done;
    do {
        asm volatile(
            "{\n\t.reg .pred p;\n\t"
            "mbarrier.try_wait.parity.acquire.cta.shared::cta.b64 p, [%1], %2, 0x989680;\n\t"
            "selp.b32 %0, 1, 0, p;\n\t}"
            : "=r"(done) : "r"(addr), "r"(parity) : "memory");
    } while (!done);
}

// ---------------------------------------------------------------------------
// Kernel A: per-row min/max of seg channel 1 (8-deep explicit load batch),
// fused with the trimmed WLS fit by the elected last block per image.
// Grid = B*32, 512 thr, warp owns one row. (R9 version — measured best.)
// ---------------------------------------------------------------------------
__global__ void __launch_bounds__(512) minmax_fit_kernel(const float* __restrict__ seg)
{
    const int b    = blockIdx.x >> 5;
    const int blk  = blockIdx.x & 31;
    const int tid  = threadIdx.x;
    const int lane = tid & 31;
    const int warp = tid >> 5;

    const int h = blk * 16 + warp;
    const float4* row = (const float4*)(seg + (size_t)b * HH * WW * 2
                                            + (size_t)h * WW * 2);

    const float4 v0 = row[lane +   0];
    const float4 v1 = row[lane +  32];
    const float4 v2 = row[lane +  64];
    const float4 v3 = row[lane +  96];
    const float4 v4 = row[lane + 128];
    const float4 v5 = row[lane + 160];
    const float4 v6 = row[lane + 192];
    const float4 v7 = row[lane + 224];

    int mn = WW, mx = -1;
    #define MM_ACC(v, base)                                                    \
        do {                                                                   \
            const int p0 = 2 * (lane + (base));                                \
            if ((v).y > 0.0f) { mn = min(mn, p0);     mx = max(mx, p0); }      \
            if ((v).w > 0.0f) { mn = min(mn, p0 + 1); mx = max(mx, p0 + 1); }  \
        } while (0)
    MM_ACC(v0,   0); MM_ACC(v1,  32); MM_ACC(v2,  64); MM_ACC(v3,  96);
    MM_ACC(v4, 128); MM_ACC(v5, 160); MM_ACC(v6, 192); MM_ACC(v7, 224);
    #undef MM_ACC

    #pragma unroll
    for (int o = 16; o; o >>= 1) {
        mn = min(mn, __shfl_down_sync(0xffffffffu, mn, o));
        mx = max(mx, __shfl_down_sync(0xffffffffu, mx, o));
    }
    if (lane == 0) {
        g_xmin[b * HH + h] = mn;
        g_xmax[b * HH + h] = mx;
    }
    __threadfence();

    __shared__ int isLast;
    __syncthreads();
    if (tid == 0) isLast = (atomicAdd(&g_count[b], 1) == 31);
    __syncthreads();
    if (!isLast) return;
    __threadfence();

    const int xmin_i = __ldcg(&g_xmin[b * HH + tid]);
    const int xmax_i = __ldcg(&g_xmax[b * HH + tid]);
    const int valid  = (xmax_i >= 0 && xmin_i != xmax_i) ? 1 : 0;

    __shared__ int   wtot[16];
    __shared__ float acc[7];
    unsigned bal = __ballot_sync(0xffffffffu, valid);
    int pre = __popc(bal & ((1u << lane) - 1u));
    if (lane == 0) wtot[warp] = __popc(bal);
    if (tid < 7) acc[tid] = 0.0f;
    __syncthreads();

    int off = 0, nvalid = 0;
    #pragma unroll
    for (int i = 0; i < 16; i++) {
        int t = wtot[i];
        nvalid += t;
        if (i < warp) off += t;
    }
    const int rank = off + pre;

    int drop = (int)((float)nvalid * 0.15f);   // trunc, matches astype(int32)
    if (drop < 1) drop = 1;
    const int keep = valid && (rank >= drop) && (rank < nvalid - drop);

    const float w  = keep ? 1.0f : 0.0f;
    const float y  = (float)tid;
    const float xl = (float)xmin_i;
    const float xr = (float)xmax_i;

    float s0 = w, s1 = w * y, s2 = w * y * y;
    float s3 = w * xl, s4 = w * y * xl;
    float s5 = w * xr, s6 = w * y * xr;

    #pragma unroll
    for (int o = 16; o; o >>= 1) {
        s0 += __shfl_down_sync(0xffffffffu, s0, o);
        s1 += __shfl_down_sync(0xffffffffu, s1, o);
        s2 += __shfl_down_sync(0xffffffffu, s2, o);
        s3 += __shfl_down_sync(0xffffffffu, s3, o);
        s4 += __shfl_down_sync(0xffffffffu, s4, o);
        s5 += __shfl_down_sync(0xffffffffu, s5, o);
        s6 += __shfl_down_sync(0xffffffffu, s6, o);
    }
    if (lane == 0) {
        atomicAdd(&acc[0], s0); atomicAdd(&acc[1], s1); atomicAdd(&acc[2], s2);
        atomicAdd(&acc[3], s3); atomicAdd(&acc[4], s4);
        atomicAdd(&acc[5], s5); atomicAdd(&acc[6], s6);
    }
    __syncthreads();

    if (tid == 0) {
        const float Sw  = acc[0], Sy  = acc[1], Syy = acc[2];
        const float Sxl = acc[3], Sxyl = acc[4];
        const float Sxr = acc[5], Sxyr = acc[6];

        const float det  = Syy * Sw - Sy * Sy;
        const float safe = (det > 0.0f) ? det : 1.0f;

        float sl_l = (Sw * Sxyl - Sy * Sxl) / safe;
        float ic_l = (-Sy * Sxyl + Syy * Sxl) / safe;
        float sl_r = (Sw * Sxyr - Sy * Sxr) / safe;
        float ic_r = (-Sy * Sxyr + Syy * Sxr) / safe;
        if (!(det > 0.0f)) { sl_l = ic_l = sl_r = ic_r = 0.0f; }

        g_theta[b] = make_float4(sl_l, ic_l, sl_r, ic_r);
        g_count[b] = 0;              // reset for the next graph replay
    }
}

// ---------------------------------------------------------------------------
// Kernel C: one block per (bn, chunk); chunk = 128 contiguous rows = 256KB,
// streamed as 16 x 16KB stages through a 4-deep cp.async.bulk + mbarrier
// pipeline into smem. Threads reduce each stage from smem.
// 512 thr: g = tid>>7 (row pair group), c = tid&127 (columns 4c..4c+3).
// Stage i rows: local r = 8i + 2g + j, j in {0,1}.
// ---------------------------------------------------------------------------
__global__ void __launch_bounds__(512) size_kernel(const float* __restrict__ pad,
                                                   float* __restrict__ out,
                                                   int N)
{
    extern __shared__ char smem[];
    float*    su      = (float*)(smem + SU_OFF);
    float*    su2     = (float*)(smem + SU2_OFF);
    float*    scol    = (float*)(smem + SCOL_OFF);
    unsigned* grpmask = (unsigned*)(smem + GRP_OFF);
    float*    sred    = (float*)(smem + SRED_OFF);
    float*    svert   = (float*)(smem + SVERT_OFF);

    const int bn   = blockIdx.x >> 2;
    const int ch   = blockIdx.x & 3;
    const int b    = bn / N;
    const int tid  = threadIdx.x;
    const int lane = tid & 31;
    const int warp = tid >> 5;
    const int g    = tid >> 7;
    const int c    = tid & 127;
    const int h0   = ch * CHROWS;

    const uint32_t sbase = smem_u32(smem);
    const uint32_t mbar0 = sbase + MBAR_OFF;
    const uint32_t buf0  = sbase + BUF_OFF;

    // init pipeline barriers
    if (tid == 0) {
        #pragma unroll
        for (int s = 0; s < STAGES; s++) MBAR_INIT(mbar0 + 8 * s, 1);
        asm volatile("fence.proxy.async.shared::cta;" ::: "memory");
    }

    // reduction-free unit prologue from theta
    if (tid < CHROWS) {
        const float4 th = g_theta[b];
        const float y = (float)(h0 + tid);
        float width = (y * th.z + th.w) - (y * th.x + th.y);
        width = fmaxf(width, 1.0f);
        const float u = 3.25f / width;
        su [tid] = u;
        su2[tid] = u * u;
    }
    scol[tid] = 0.0f;
    if (tid < 4) grpmask[tid] = 0u;
    __syncthreads();

    const char* gsrc = (const char*)(pad + (size_t)bn * HH * WW + (size_t)h0 * WW);

    // prologue: fill the pipe
    if (tid == 0) {
        #pragma unroll
        for (int s = 0; s < STAGES; s++) {
            MBAR_EXPECT_TX(mbar0 + 8 * s, STAGE_BYTES);
            BULK_G2S(buf0 + s * STAGE_BYTES, gsrc + (size_t)s * STAGE_BYTES,
                     STAGE_BYTES, mbar0 + 8 * s);
        }
    }

    float4 colacc = make_float4(0.f, 0.f, 0.f, 0.f);
    float  inst   = 0.0f;
    unsigned lm   = 0u;

    for (int i = 0; i < NSTG; i++) {
        const int slot = i & (STAGES - 1);
        mbar_wait_parity(mbar0 + 8 * slot, (i >> 2) & 1);

        const float4* bp = (const float4*)(smem + BUF_OFF + slot * STAGE_BYTES);
        #pragma unroll
        for (int j = 0; j < 2; j++) {
            const int rloc = i * 8 + g * 2 + j;            // local row
            const float4 v = bp[(g * 2 + j) * (WW / 4) + c];
            const float u1 = su[rloc], u2 = su2[rloc];
            colacc.x = fmaf(u1, v.x, colacc.x);
            colacc.y = fmaf(u1, v.y, colacc.y);
            colacc.z = fmaf(u1, v.z, colacc.z);
            colacc.w = fmaf(u1, v.w, colacc.w);
            inst = fmaf(u2, (v.x + v.y) + (v.z + v.w), inst);
            if (v.x > 0.5f || v.y > 0.5f || v.z > 0.5f || v.w > 0.5f)
                lm |= (1u << (i * 2 + j));
        }
        __syncthreads();            // all reads of this slot done

        if (tid == 0 && i + STAGES < NSTG) {
            MBAR_EXPECT_TX(mbar0 + 8 * slot, STAGE_BYTES);
            BULK_G2S(buf0 + slot * STAGE_BYTES,
                     gsrc + (size_t)(i + STAGES) * STAGE_BYTES,
                     STAGE_BYTES, mbar0 + 8 * slot);
        }
    }

    // row-occupied bits: OR across the 4 warps of each group
    {
        unsigned m = __reduce_or_sync(0xffffffffu, lm);
        if (lane == 0 && m) atomicOr(&grpmask[g], m);
    }

    // per-column sums: combine 4 row-groups via shared atomics
    atomicAdd(&scol[4 * c + 0], colacc.x);
    atomicAdd(&scol[4 * c + 1], colacc.y);
    atomicAdd(&scol[4 * c + 2], colacc.z);
    atomicAdd(&scol[4 * c + 3], colacc.w);

    // instance partial (block sum)
    float s = inst;
    #pragma unroll
    for (int o = 16; o; o >>= 1) s += __shfl_down_sync(0xffffffffu, s, o);
    if (lane == 0) sred[warp] = s;
    __syncthreads();

    // vertical partial: local row r -> group (r&7)>>1, bit (r>>3)*2 + (r&1)
    float vv = 0.0f;
    if (tid < CHROWS) {
        const int gg = (tid & 7) >> 1;
        const int kk = ((tid >> 3) << 1) | (tid & 1);
        const unsigned bit = (grpmask[gg] >> kk) & 1u;
        vv = bit ? su[tid] : 0.0f;
    }
    #pragma unroll
    for (int o = 16; o; o >>= 1) vv += __shfl_down_sync(0xffffffffu, vv, o);
    if (lane == 0 && warp < 4) svert[warp] = vv;
    __syncthreads();

    if (tid == 0) {
        float ti = 0.0f;
        #pragma unroll
        for (int i = 0; i < 16; i++) ti += sred[i];
        float tv = (svert[0] + svert[1]) + (svert[2] + svert[3]);
        g_part[bn][ch][0] = ti;
        g_part[bn][ch][1] = tv;
    }

    // column partials to scratch (coalesced)
    g_colp[bn][ch][tid] = scol[tid];
    __threadfence();

    // elect last chunk-block of this slab to combine
    __shared__ int isLastC;
    __syncthreads();
    if (tid == 0) isLastC = (atomicAdd(&g_cnt[bn], 1) == NCH - 1);
    __syncthreads();
    if (!isLastC) return;
    __threadfence();

    float colsum = __ldcg(&g_colp[bn][0][tid]);
    colsum += __ldcg(&g_colp[bn][1][tid]);
    colsum += __ldcg(&g_colp[bn][2][tid]);
    colsum += __ldcg(&g_colp[bn][3][tid]);

    float m = colsum;
    #pragma unroll
    for (int o = 16; o; o >>= 1) m = fmaxf(m, __shfl_down_sync(0xffffffffu, m, o));
    if (lane == 0) sred[warp] = m;
    __syncthreads();

    if (tid == 0) {
        float hmax = sred[0];
        #pragma unroll
        for (int i = 1; i < 16; i++) hmax = fmaxf(hmax, sred[i]);

        float ti = 0.0f, tv = 0.0f;
        #pragma unroll
        for (int i = 0; i < NCH; i++) {
            ti += __ldcg(&g_part[bn][i][0]);
            tv += __ldcg(&g_part[bn][i][1]);
        }
        out[bn * 3 + 0] = ti;
        out[bn * 3 + 1] = hmax;
        out[bn * 3 + 2] = tv;

        g_cnt[bn] = 0;               // reset for the next graph replay
    }
}

// ---------------------------------------------------------------------------
extern "C" void kernel_launch(void* const* d_in, const int* in_sizes, int n_in,
                              void* d_out, int out_size)
{
    const float* seg = (const float*)d_in[0];   // [B, H, W, 2]
    const float* pad = (const float*)d_in[1];   // [B, N, H, W]
    float* out = (float*)d_out;                 // [B, N, 3]

    const int B = in_sizes[0] / (HH * WW * 2);
    const int N = in_sizes[1] / (B * HH * WW);

    static int attr_set = 0;
    if (!attr_set) {
        cudaFuncSetAttribute(size_kernel,
                             cudaFuncAttributeMaxDynamicSharedMemorySize, SMEM_DYN);
        attr_set = 1;
    }

    minmax_fit_kernel<<<B * 32, 512>>>(seg);
    size_kernel<<<B * N * NCH, 512, SMEM_DYN>>>(pad, out, N);
}

// round 12
// speedup vs baseline: 1.0784x; 1.0784x over previous
#include <cuda_runtime.h>
#include <cstdint>

#define HH 512
#define WW 512
#define MAXB 16
#define MAXBN 512          // max B*N slabs
#define NCH 4              // H-chunks per slab
#define CHROWS (HH / NCH)  // 128 rows per chunk

// Scratch (device globals — zero-initialized at module load; no allocation).
__device__ int    g_xmin [MAXB * HH];
__device__ int    g_xmax [MAXB * HH];
__device__ float4 g_theta[MAXB];                 // {sl_l, ic_l, sl_r, ic_r}
__device__ float  g_colp [MAXBN][NCH][WW];       // per-chunk column sums
__device__ float  g_part [MAXBN][NCH][2];        // per-chunk {inst, vert}
__device__ int    g_cnt  [MAXBN];                // size-chunk combine election

// ---------------------------------------------------------------------------
// Kernel A: per-row min/max positive column of seg channel 1. Pure stream,
// explicit 8-deep load batch per lane. Grid = B*32, 512 thr, warp owns a row.
// Triggers programmatic completion right after its stores so the fit kernel
// can begin while tail blocks drain.
// ---------------------------------------------------------------------------
__global__ void __launch_bounds__(512) minmax_kernel(const float* __restrict__ seg)
{
    const int b    = blockIdx.x >> 5;
    const int blk  = blockIdx.x & 31;
    const int lane = threadIdx.x & 31;
    const int warp = threadIdx.x >> 5;

    const int h = blk * 16 + warp;
    const float4* row = (const float4*)(seg + (size_t)b * HH * WW * 2
                                            + (size_t)h * WW * 2);

    const float4 v0 = row[lane +   0];
    const float4 v1 = row[lane +  32];
    const float4 v2 = row[lane +  64];
    const float4 v3 = row[lane +  96];
    const float4 v4 = row[lane + 128];
    const float4 v5 = row[lane + 160];
    const float4 v6 = row[lane + 192];
    const float4 v7 = row[lane + 224];

    int mn = WW, mx = -1;
    #define MM_ACC(v, base)                                                    \
        do {                                                                   \
            const int p0 = 2 * (lane + (base));                                \
            if ((v).y > 0.0f) { mn = min(mn, p0);     mx = max(mx, p0); }      \
            if ((v).w > 0.0f) { mn = min(mn, p0 + 1); mx = max(mx, p0 + 1); }  \
        } while (0)
    MM_ACC(v0,   0); MM_ACC(v1,  32); MM_ACC(v2,  64); MM_ACC(v3,  96);
    MM_ACC(v4, 128); MM_ACC(v5, 160); MM_ACC(v6, 192); MM_ACC(v7, 224);
    #undef MM_ACC

    #pragma unroll
    for (int o = 16; o; o >>= 1) {
        mn = min(mn, __shfl_down_sync(0xffffffffu, mn, o));
        mx = max(mx, __shfl_down_sync(0xffffffffu, mx, o));
    }
    if (lane == 0) {
        g_xmin[b * HH + h] = mn;
        g_xmax[b * HH + h] = mx;
    }
    __threadfence();
    cudaTriggerProgrammaticLaunchCompletion();
}

// ---------------------------------------------------------------------------
// Kernel B: trimmed weighted-LS fit -> theta per image. Grid = B, tiny.
// PDL-dependent on kernel A: gridsync before reading g_xmin/g_xmax.
// ---------------------------------------------------------------------------
__global__ void __launch_bounds__(512) fit_kernel()
{
    const int b    = blockIdx.x;
    const int tid  = threadIdx.x;
    const int lane = tid & 31;
    const int warp = tid >> 5;

    __shared__ int   wtot[16];
    __shared__ float acc[7];
    if (tid < 7) acc[tid] = 0.0f;

    cudaGridDependencySynchronize();          // wait for minmax grid

    const int xmin_i = g_xmin[b * HH + tid];
    const int xmax_i = g_xmax[b * HH + tid];
    const int valid  = (xmax_i >= 0 && xmin_i != xmax_i) ? 1 : 0;

    unsigned bal = __ballot_sync(0xffffffffu, valid);
    int pre = __popc(bal & ((1u << lane) - 1u));
    if (lane == 0) wtot[warp] = __popc(bal);
    __syncthreads();

    int off = 0, nvalid = 0;
    #pragma unroll
    for (int i = 0; i < 16; i++) {
        int t = wtot[i];
        nvalid += t;
        if (i < warp) off += t;
    }
    const int rank = off + pre;

    int drop = (int)((float)nvalid * 0.15f);   // trunc, matches astype(int32)
    if (drop < 1) drop = 1;
    const int keep = valid && (rank >= drop) && (rank < nvalid - drop);

    const float w  = keep ? 1.0f : 0.0f;
    const float y  = (float)tid;
    const float xl = (float)xmin_i;
    const float xr = (float)xmax_i;

    float s0 = w, s1 = w * y, s2 = w * y * y;
    float s3 = w * xl, s4 = w * y * xl;
    float s5 = w * xr, s6 = w * y * xr;

    #pragma unroll
    for (int o = 16; o; o >>= 1) {
        s0 += __shfl_down_sync(0xffffffffu, s0, o);
        s1 += __shfl_down_sync(0xffffffffu, s1, o);
        s2 += __shfl_down_sync(0xffffffffu, s2, o);
        s3 += __shfl_down_sync(0xffffffffu, s3, o);
        s4 += __shfl_down_sync(0xffffffffu, s4, o);
        s5 += __shfl_down_sync(0xffffffffu, s5, o);
        s6 += __shfl_down_sync(0xffffffffu, s6, o);
    }
    if (lane == 0) {
        atomicAdd(&acc[0], s0); atomicAdd(&acc[1], s1); atomicAdd(&acc[2], s2);
        atomicAdd(&acc[3], s3); atomicAdd(&acc[4], s4);
        atomicAdd(&acc[5], s5); atomicAdd(&acc[6], s6);
    }
    __syncthreads();

    if (tid == 0) {
        const float Sw  = acc[0], Sy  = acc[1], Syy = acc[2];
        const float Sxl = acc[3], Sxyl = acc[4];
        const float Sxr = acc[5], Sxyr = acc[6];

        const float det  = Syy * Sw - Sy * Sy;
        const float safe = (det > 0.0f) ? det : 1.0f;

        float sl_l = (Sw * Sxyl - Sy * Sxl) / safe;
        float ic_l = (-Sy * Sxyl + Syy * Sxl) / safe;
        float sl_r = (Sw * Sxyr - Sy * Sxr) / safe;
        float ic_r = (-Sy * Sxyr + Syy * Sxr) / safe;
        if (!(det > 0.0f)) { sl_l = ic_l = sl_r = ic_r = 0.0f; }

        g_theta[b] = make_float4(sl_l, ic_l, sl_r, ic_r);
        __threadfence();
    }
    __syncthreads();
    cudaTriggerProgrammaticLaunchCompletion();
}

// ---------------------------------------------------------------------------
// Kernel C: one block per (bn, chunk); chunk = 128 rows. PDL-dependent on the
// fit: data-independent prologue first, gridsync, then the reduction-free
// theta prologue and the plain-float4 streaming loop (measured-best config).
// 512 thr = 4 row-groups x 128 col-threads; thread (g, c) owns columns
// 4c..4c+3, local rows g, g+4, ..., g+124.
// ---------------------------------------------------------------------------
__global__ void __launch_bounds__(512) size_kernel(const float* __restrict__ pad,
                                                   float* __restrict__ out,
                                                   int N)
{
    const int bn   = blockIdx.x >> 2;
    const int ch   = blockIdx.x & 3;
    const int b    = bn / N;
    const int tid  = threadIdx.x;
    const int lane = tid & 31;
    const int warp = tid >> 5;
    const int g    = tid >> 7;        // row group 0..3
    const int c    = tid & 127;       // column group: columns 4c..4c+3
    const int h0   = ch * CHROWS;     // first global row of this chunk

    __shared__ float    su [CHROWS];
    __shared__ float    su2[CHROWS];
    __shared__ float    scol[WW];
    __shared__ unsigned grpmask[4];
    __shared__ float    sred[16];

    // data-independent prologue (overlaps predecessor execution under PDL)
    scol[tid] = 0.0f;
    if (tid < 4) grpmask[tid] = 0u;
    const float4* p = (const float4*)(pad + (size_t)bn * HH * WW
                                          + (size_t)h0 * WW) + c;

    cudaGridDependencySynchronize();          // wait for fit grid

    if (tid < CHROWS) {
        const float4 th = g_theta[b];         // {sl_l, ic_l, sl_r, ic_r}
        const float y = (float)(h0 + tid);
        float width = (y * th.z + th.w) - (y * th.x + th.y);
        width = fmaxf(width, 1.0f);
        const float u = 3.25f / width;
        su [tid] = u;
        su2[tid] = u * u;
    }
    __syncthreads();

    float4 colacc = make_float4(0.f, 0.f, 0.f, 0.f);
    float  inst   = 0.0f;
    unsigned lm   = 0u;

    #pragma unroll 8
    for (int k = 0; k < 32; k++) {
        const int h = g + 4 * k;      // local row
        const float4 v = p[(size_t)h * (WW / 4)];
        const float u1 = su[h], u2 = su2[h];
        colacc.x = fmaf(u1, v.x, colacc.x);
        colacc.y = fmaf(u1, v.y, colacc.y);
        colacc.z = fmaf(u1, v.z, colacc.z);
        colacc.w = fmaf(u1, v.w, colacc.w);
        inst = fmaf(u2, (v.x + v.y) + (v.z + v.w), inst);
        if (v.x > 0.5f || v.y > 0.5f || v.z > 0.5f || v.w > 0.5f)
            lm |= (1u << k);
    }

    // row-occupied bits: OR across the 4 warps of each group
    {
        unsigned m = __reduce_or_sync(0xffffffffu, lm);
        if (lane == 0 && m) atomicOr(&grpmask[g], m);
    }

    // per-column sums: combine 4 row-groups via shared atomics
    atomicAdd(&scol[4 * c + 0], colacc.x);
    atomicAdd(&scol[4 * c + 1], colacc.y);
    atomicAdd(&scol[4 * c + 2], colacc.z);
    atomicAdd(&scol[4 * c + 3], colacc.w);

    // instance partial (block sum)
    float s = inst;
    #pragma unroll
    for (int o = 16; o; o >>= 1) s += __shfl_down_sync(0xffffffffu, s, o);
    if (lane == 0) sred[warp] = s;
    __syncthreads();

    // vertical partial: local row r handled by group r&3, iteration r>>2
    float vv = 0.0f;
    if (tid < CHROWS) {
        const unsigned bit = (grpmask[tid & 3] >> (tid >> 2)) & 1u;
        vv = bit ? su[tid] : 0.0f;
    }
    #pragma unroll
    for (int o = 16; o; o >>= 1) vv += __shfl_down_sync(0xffffffffu, vv, o);

    __shared__ float svert[4];
    if (lane == 0 && warp < 4) svert[warp] = vv;
    __syncthreads();

    if (tid == 0) {
        float ti = 0.0f;
        #pragma unroll
        for (int i = 0; i < 16; i++) ti += sred[i];
        float tv = (svert[0] + svert[1]) + (svert[2] + svert[3]);
        g_part[bn][ch][0] = ti;
        g_part[bn][ch][1] = tv;
    }

    // column partials to scratch (coalesced)
    g_colp[bn][ch][tid] = scol[tid];
    __threadfence();

    // elect last chunk-block of this slab to combine
    __shared__ int isLastC;
    __syncthreads();
    if (tid == 0) isLastC = (atomicAdd(&g_cnt[bn], 1) == NCH - 1);
    __syncthreads();
    if (!isLastC) return;
    __threadfence();

    // horizontal: per-column sum over chunks (fixed order), then block max
    float colsum = __ldcg(&g_colp[bn][0][tid]);
    colsum += __ldcg(&g_colp[bn][1][tid]);
    colsum += __ldcg(&g_colp[bn][2][tid]);
    colsum += __ldcg(&g_colp[bn][3][tid]);

    float m = colsum;
    #pragma unroll
    for (int o = 16; o; o >>= 1) m = fmaxf(m, __shfl_down_sync(0xffffffffu, m, o));
    if (lane == 0) sred[warp] = m;
    __syncthreads();

    if (tid == 0) {
        float hmax = sred[0];
        #pragma unroll
        for (int i = 1; i < 16; i++) hmax = fmaxf(hmax, sred[i]);

        float ti = 0.0f, tv = 0.0f;
        #pragma unroll
        for (int i = 0; i < NCH; i++) {
            ti += __ldcg(&g_part[bn][i][0]);
            tv += __ldcg(&g_part[bn][i][1]);
        }
        out[bn * 3 + 0] = ti;
        out[bn * 3 + 1] = hmax;
        out[bn * 3 + 2] = tv;

        g_cnt[bn] = 0;               // reset for the next graph replay
    }
}

// ---------------------------------------------------------------------------
extern "C" void kernel_launch(void* const* d_in, const int* in_sizes, int n_in,
                              void* d_out, int out_size)
{
    const float* seg = (const float*)d_in[0];   // [B, H, W, 2]
    const float* pad = (const float*)d_in[1];   // [B, N, H, W]
    float* out = (float*)d_out;                 // [B, N, 3]

    const int B = in_sizes[0] / (HH * WW * 2);
    const int N = in_sizes[1] / (B * HH * WW);

    // plain launch for kernel A
    minmax_kernel<<<B * 32, 512>>>(seg);

    // PDL attribute: allow overlap with predecessor; dependent kernels call
    // cudaGridDependencySynchronize() before touching predecessor data.
    cudaLaunchAttribute attr[1];
    attr[0].id = cudaLaunchAttributeProgrammaticStreamSerialization;
    attr[0].val.programmaticStreamSerializationAllowed = 1;

    cudaLaunchConfig_t cfgB = {};
    cfgB.gridDim  = dim3(B, 1, 1);
    cfgB.blockDim = dim3(512, 1, 1);
    cfgB.attrs    = attr;
    cfgB.numAttrs = 1;
    cudaLaunchKernelEx(&cfgB, fit_kernel);

    cudaLaunchConfig_t cfgC = {};
    cfgC.gridDim  = dim3(B * N * NCH, 1, 1);
    cfgC.blockDim = dim3(512, 1, 1);
    cfgC.attrs    = attr;
    cfgC.numAttrs = 1;
    cudaLaunchKernelEx(&cfgC, size_kernel, (const float*)pad, (float*)out, (int)N);
}